// round 6
// baseline (speedup 1.0000x reference)
#include <cuda_runtime.h>
#include <math.h>
#include <stdint.h>

// Fixed shape: H=1024, B=64, T=1024
#define BB 64
#define TS 1024
#define HS 1024
#define CL 4                       // cluster size (h split 4 ways)
#define HR 256                     // h rows per CTA
#define TCH 64                     // t per chunk
#define NCH 16                     // chunks per b
#define NBC 2                      // b per cluster
#define NUNITS (NBC * NCH)         // 32
#define GRID 128
#define THREADS 384
#define DEPTH 3
#define TILE_FLOATS (HR * TCH)     // 16384
#define TILE_BYTES  (TILE_FLOATS * 4)
#define HSTRIDE ((size_t)BB * TS)

// dynamic smem layout (bytes)
#define OFF_MB   (DEPTH * TILE_BYTES)   // ring mbars: full s*16, empty s*16+8
#define OFF_SMB  (OFF_MB + 48)          // stats mbar (count 3)
#define OFF_DMB  (OFF_MB + 56)          // denom mbar (count 3)
#define OFF_SRED (OFF_MB + 64)          // sredA/B/C/D: 4 * 2048 B, [w][tq] float4
#define OFF_INA  (OFF_SRED + 8192)      // inbox stats: [par][arr3][rank][tq] float4 = 6144
#define OFF_IND  (OFF_INA + 6144)       // inbox denom: [par][rank][tq] float4 = 2048
#define SMEM_BYTES (OFF_IND + 2048)     // 213056 B

__device__ __forceinline__ uint32_t smem_u32(const void* p) {
    return (uint32_t)__cvta_generic_to_shared(p);
}
__device__ __forceinline__ void mbar_init(uint32_t a, uint32_t cnt) {
    asm volatile("mbarrier.init.shared.b64 [%0], %1;" :: "r"(a), "r"(cnt) : "memory");
}
__device__ __forceinline__ void mbar_arrive(uint32_t a) {
    asm volatile("mbarrier.arrive.shared.b64 _, [%0];" :: "r"(a) : "memory");
}
__device__ __forceinline__ uint32_t mapa_u32(uint32_t a, uint32_t rank) {
    uint32_t r;
    asm volatile("mapa.shared::cluster.u32 %0, %1, %2;" : "=r"(r) : "r"(a), "r"(rank));
    return r;
}
__device__ __forceinline__ void st_cluster_v4(uint32_t a, float4 v) {
    asm volatile("st.shared::cluster.v4.f32 [%0], {%1,%2,%3,%4};"
                 :: "r"(a), "f"(v.x), "f"(v.y), "f"(v.z), "f"(v.w) : "memory");
}
__device__ __forceinline__ void mbar_arrive_rel_cluster(uint32_t remote) {
    asm volatile("mbarrier.arrive.release.cluster.shared::cluster.b64 _, [%0];"
                 :: "r"(remote) : "memory");
}
__device__ __forceinline__ void cp16(uint32_t dst, const float* src) {
    asm volatile("cp.async.cg.shared.global [%0], [%1], 16;" :: "r"(dst), "l"(src));
}

#define MB_WAIT_CTA(addr, parity) do {                                          \
    uint32_t _m = (addr), _p = (parity), _d;                                    \
    asm volatile("{\n\t.reg .pred p;\n\t"                                       \
        "mbarrier.try_wait.parity.acquire.cta.shared::cta.b64 p, [%1], %2;\n\t" \
        "selp.b32 %0, 1, 0, p;\n\t}" : "=r"(_d) : "r"(_m), "r"(_p) : "memory"); \
    if (!_d) {                                                                  \
        asm volatile("{\n\t.reg .pred P1;\n\tW%=:\n\t"                          \
            "mbarrier.try_wait.parity.acquire.cta.shared::cta.b64 P1, [%0], %1, 0x989680;\n\t" \
            "@P1 bra.uni D%=;\n\tbra.uni W%=;\n\tD%=:\n\t}"                     \
            :: "r"(_m), "r"(_p) : "memory");                                    \
    }                                                                           \
} while (0)

#define MB_WAIT_CLU(addr, parity) do {                                          \
    uint32_t _m = (addr), _p = (parity), _d;                                    \
    asm volatile("{\n\t.reg .pred p;\n\t"                                       \
        "mbarrier.try_wait.parity.acquire.cluster.shared::cta.b64 p, [%1], %2;\n\t" \
        "selp.b32 %0, 1, 0, p;\n\t}" : "=r"(_d) : "r"(_m), "r"(_p) : "memory"); \
    if (!_d) {                                                                  \
        asm volatile("{\n\t.reg .pred P1;\n\tW%=:\n\t"                          \
            "mbarrier.try_wait.parity.acquire.cluster.shared::cta.b64 P1, [%0], %1, 0x989680;\n\t" \
            "@P1 bra.uni D%=;\n\tbra.uni W%=;\n\tD%=:\n\t}"                     \
            :: "r"(_m), "r"(_p) : "memory");                                    \
    }                                                                           \
} while (0)

__global__ void __launch_bounds__(THREADS, 1) __cluster_dims__(CL, 1, 1)
attn_main(const float* __restrict__ dh, const float* __restrict__ enc,
          float* __restrict__ out) {
    extern __shared__ float smem[];
    const uint32_t sbase = smem_u32(smem);
    const uint32_t MB  = sbase + OFF_MB;
    const uint32_t SMB = sbase + OFF_SMB;
    const uint32_t DMB = sbase + OFF_DMB;
    float4* sredA = reinterpret_cast<float4*>((char*)smem + OFF_SRED);          // [w*16+tq]
    float4* sredB = sredA + 128;
    float4* sredC = sredB + 128;
    float4* sredD = sredC + 128;
    float4* inbox = reinterpret_cast<float4*>((char*)smem + OFF_INA); // [par][arr][rank][tq]
    float4* inD   = reinterpret_cast<float4*>((char*)smem + OFF_IND); // [par][rank][tq]

    const int tid = threadIdx.x;
    const int w = tid >> 5, l = tid & 31;
    uint32_t rank;
    asm("mov.u32 %0, %%cluster_ctarank;" : "=r"(rank));
    const int cluster = blockIdx.x >> 2;

    if (tid == 0) {
        #pragma unroll
        for (int s = 0; s < DEPTH; ++s) {
            mbar_init(MB + s * 16, 128);       // full: 128 producer threads
            mbar_init(MB + s * 16 + 8, 256);   // empty: 256 consumer threads
        }
        mbar_init(SMB, 3);                     // 3 peer arrivals per unit
        mbar_init(DMB, 3);
    }
    __syncthreads();
    asm volatile("barrier.cluster.arrive.aligned;" ::: "memory");
    asm volatile("barrier.cluster.wait.aligned;" ::: "memory");

    if (w >= 8) {
        // ---------------- producers (warps 8..11) ----------------
        const int pw = w - 8;
        const int lr = l >> 4, lc = l & 15;
        for (int n = 0; n < NUNITS; ++n) {
            const int s = n % DEPTH;
            if (n >= DEPTH)
                MB_WAIT_CTA(MB + s * 16 + 8, ((n / DEPTH) & 1) ^ 1);
            const int b  = cluster * NBC + (n >> 4);
            const int t0 = (n & 15) * TCH;
            const float* gb = enc + (size_t)(rank * HR) * HSTRIDE
                                  + (size_t)b * TS + t0 + lc * 4;
            const uint32_t d0 = sbase + (uint32_t)s * TILE_BYTES + lc * 16;
            #pragma unroll
            for (int i = 0; i < 32; ++i) {
                const int row = pw * 64 + 2 * i + lr;
                cp16(d0 + (uint32_t)row * 256, gb + (size_t)row * HSTRIDE);
            }
            asm volatile("cp.async.commit_group;" ::: "memory");
            if (n >= 1) {
                asm volatile("cp.async.wait_group 1;" ::: "memory");
                mbar_arrive(MB + ((n - 1) % DEPTH) * 16);
            }
        }
        asm volatile("cp.async.wait_group 0;" ::: "memory");
        mbar_arrive(MB + ((NUNITS - 1) % DEPTH) * 16);
    } else {
        // ---------------- consumers (warps 0..7) ----------------
        const int tq = l & 15;           // t-quad: t = 4*tq .. 4*tq+3
        const int hr = l >> 4;           // row-half within warp
        const int r0 = w * 32 + hr * 16; // 16 consecutive rows per thread

        float dhv[16];
        float acc[16];
        #pragma unroll
        for (int i = 0; i < 16; ++i) acc[i] = 0.0f;

        for (int n = 0; n < NUNITS; ++n) {
            const int s  = n % DEPTH;
            const int pa = n & 1;
            const int b  = cluster * NBC + (n >> 4);

            if ((n & 15) == 0) {   // new b: load dh slice
                #pragma unroll
                for (int k = 0; k < 4; ++k) {
                    const float4 d = __ldg(reinterpret_cast<const float4*>(
                        dh + b * HS + rank * HR + r0 + 4 * k));
                    dhv[4*k] = d.x; dhv[4*k+1] = d.y; dhv[4*k+2] = d.z; dhv[4*k+3] = d.w;
                }
            }

            MB_WAIT_CTA(MB + s * 16, (n / DEPTH) & 1);

            // tile slice -> registers (16 x LDS.128, conflict-free)
            float4 v[16];
            const float* tb = smem + (size_t)s * TILE_FLOATS + tq * 4;
            #pragma unroll
            for (int i = 0; i < 16; ++i)
                v[i] = *reinterpret_cast<const float4*>(tb + (r0 + i) * TCH);

            // local per-t stats over 16 rows
            float4 sp = {0.f,0.f,0.f,0.f};
            float4 mx = {-INFINITY,-INFINITY,-INFINITY,-INFINITY};
            float4 mn = { INFINITY, INFINITY, INFINITY, INFINITY};
            #pragma unroll
            for (int i = 0; i < 16; ++i) {
                sp.x = fmaf(v[i].x, dhv[i], sp.x); sp.y = fmaf(v[i].y, dhv[i], sp.y);
                sp.z = fmaf(v[i].z, dhv[i], sp.z); sp.w = fmaf(v[i].w, dhv[i], sp.w);
                mx.x = fmaxf(mx.x, v[i].x); mx.y = fmaxf(mx.y, v[i].y);
                mx.z = fmaxf(mx.z, v[i].z); mx.w = fmaxf(mx.w, v[i].w);
                mn.x = fminf(mn.x, v[i].x); mn.y = fminf(mn.y, v[i].y);
                mn.z = fminf(mn.z, v[i].z); mn.w = fminf(mn.w, v[i].w);
            }
            mbar_arrive(MB + s * 16 + 8);   // tile now in registers

            // combine row-halves (xor 16)
            sp.x += __shfl_xor_sync(~0u, sp.x, 16); sp.y += __shfl_xor_sync(~0u, sp.y, 16);
            sp.z += __shfl_xor_sync(~0u, sp.z, 16); sp.w += __shfl_xor_sync(~0u, sp.w, 16);
            mx.x = fmaxf(mx.x, __shfl_xor_sync(~0u, mx.x, 16));
            mx.y = fmaxf(mx.y, __shfl_xor_sync(~0u, mx.y, 16));
            mx.z = fmaxf(mx.z, __shfl_xor_sync(~0u, mx.z, 16));
            mx.w = fmaxf(mx.w, __shfl_xor_sync(~0u, mx.w, 16));
            mn.x = fminf(mn.x, __shfl_xor_sync(~0u, mn.x, 16));
            mn.y = fminf(mn.y, __shfl_xor_sync(~0u, mn.y, 16));
            mn.z = fminf(mn.z, __shfl_xor_sync(~0u, mn.z, 16));
            mn.w = fminf(mn.w, __shfl_xor_sync(~0u, mn.w, 16));
            if (hr == 0) {
                sredA[w * 16 + tq] = sp;
                sredB[w * 16 + tq] = mx;
                sredC[w * 16 + tq] = mn;
            }
            asm volatile("bar.sync 1, 256;" ::: "memory");

            // combine across 8 warps (CTA-local stats for my tq)
            float4 sC = {0.f,0.f,0.f,0.f};
            float4 xC = {-INFINITY,-INFINITY,-INFINITY,-INFINITY};
            float4 nC = { INFINITY, INFINITY, INFINITY, INFINITY};
            #pragma unroll
            for (int w2 = 0; w2 < 8; ++w2) {
                const float4 a = sredA[w2 * 16 + tq];
                const float4 xx = sredB[w2 * 16 + tq];
                const float4 nn = sredC[w2 * 16 + tq];
                sC.x += a.x; sC.y += a.y; sC.z += a.z; sC.w += a.w;
                xC.x = fmaxf(xC.x, xx.x); xC.y = fmaxf(xC.y, xx.y);
                xC.z = fmaxf(xC.z, xx.z); xC.w = fmaxf(xC.w, xx.w);
                nC.x = fminf(nC.x, nn.x); nC.y = fminf(nC.y, nn.y);
                nC.z = fminf(nC.z, nn.z); nC.w = fminf(nC.w, nn.w);
            }

            // warp 0 exports CTA stats to the 3 peers' inboxes
            if (w == 0) {
                if (l < 16) {
                    #pragma unroll
                    for (int p = 1; p < 4; ++p) {
                        const uint32_t pr = (rank + p) & 3;
                        const uint32_t base = sbase + OFF_INA + pa * 3072
                                            + (uint32_t)rank * 256 + tq * 16;
                        st_cluster_v4(mapa_u32(base,          pr), sC);
                        st_cluster_v4(mapa_u32(base + 1024,   pr), xC);
                        st_cluster_v4(mapa_u32(base + 2048,   pr), nC);
                    }
                }
                __syncwarp();
                if (l < 3)
                    mbar_arrive_rel_cluster(mapa_u32(SMB, (rank + 1 + l) & 3));
            }
            MB_WAIT_CLU(SMB, pa);

            // fold peers -> full-H stats
            #pragma unroll
            for (int p = 1; p < 4; ++p) {
                const int rr = (rank + p) & 3;
                const float4 a = inbox[pa * 192 + rr * 16 + tq];
                const float4 xx = inbox[pa * 192 + 64 + rr * 16 + tq];
                const float4 nn = inbox[pa * 192 + 128 + rr * 16 + tq];
                sC.x += a.x; sC.y += a.y; sC.z += a.z; sC.w += a.w;
                xC.x = fmaxf(xC.x, xx.x); xC.y = fmaxf(xC.y, xx.y);
                xC.z = fmaxf(xC.z, xx.z); xC.w = fmaxf(xC.w, xx.w);
                nC.x = fminf(nC.x, nn.x); nC.y = fminf(nC.y, nn.y);
                nC.z = fminf(nC.z, nn.z); nC.w = fminf(nC.w, nn.w);
            }
            float4 M;
            M.x = (sC.x >= 0.f) ? xC.x * sC.x : nC.x * sC.x;
            M.y = (sC.y >= 0.f) ? xC.y * sC.y : nC.y * sC.y;
            M.z = (sC.z >= 0.f) ? xC.z * sC.z : nC.z * sC.z;
            M.w = (sC.w >= 0.f) ? xC.w * sC.w : nC.w * sC.w;

            // exp on registers + local denominator
            float4 ds = {0.f,0.f,0.f,0.f};
            #pragma unroll
            for (int i = 0; i < 16; ++i) {
                v[i].x = __expf(fmaf(v[i].x, sC.x, -M.x)); ds.x += v[i].x;
                v[i].y = __expf(fmaf(v[i].y, sC.y, -M.y)); ds.y += v[i].y;
                v[i].z = __expf(fmaf(v[i].z, sC.z, -M.z)); ds.z += v[i].z;
                v[i].w = __expf(fmaf(v[i].w, sC.w, -M.w)); ds.w += v[i].w;
            }
            ds.x += __shfl_xor_sync(~0u, ds.x, 16); ds.y += __shfl_xor_sync(~0u, ds.y, 16);
            ds.z += __shfl_xor_sync(~0u, ds.z, 16); ds.w += __shfl_xor_sync(~0u, ds.w, 16);
            if (hr == 0) sredD[w * 16 + tq] = ds;
            asm volatile("bar.sync 1, 256;" ::: "memory");

            float4 dC = {0.f,0.f,0.f,0.f};
            #pragma unroll
            for (int w2 = 0; w2 < 8; ++w2) {
                const float4 d = sredD[w2 * 16 + tq];
                dC.x += d.x; dC.y += d.y; dC.z += d.z; dC.w += d.w;
            }
            if (w == 0) {
                if (l < 16) {
                    #pragma unroll
                    for (int p = 1; p < 4; ++p) {
                        const uint32_t pr = (rank + p) & 3;
                        const uint32_t base = sbase + OFF_IND + pa * 1024
                                            + (uint32_t)rank * 256 + tq * 16;
                        st_cluster_v4(mapa_u32(base, pr), dC);
                    }
                }
                __syncwarp();
                if (l < 3)
                    mbar_arrive_rel_cluster(mapa_u32(DMB, (rank + 1 + l) & 3));
            }
            MB_WAIT_CLU(DMB, pa);
            #pragma unroll
            for (int p = 1; p < 4; ++p) {
                const int rr = (rank + p) & 3;
                const float4 d = inD[pa * 64 + rr * 16 + tq];
                dC.x += d.x; dC.y += d.y; dC.z += d.z; dC.w += d.w;
            }
            const float4 inv = {1.0f / dC.x, 1.0f / dC.y, 1.0f / dC.z, 1.0f / dC.w};

            #pragma unroll
            for (int i = 0; i < 16; ++i) {
                float a = fmaf(v[i].x, inv.x, acc[i]);
                a = fmaf(v[i].y, inv.y, a);
                a = fmaf(v[i].z, inv.z, a);
                acc[i] = fmaf(v[i].w, inv.w, a);
            }

            // end of this b: reduce across the 16 tq lanes and write out
            if ((n & 15) == 15) {
                #pragma unroll
                for (int off = 1; off <= 8; off <<= 1)
                    #pragma unroll
                    for (int i = 0; i < 16; ++i)
                        acc[i] += __shfl_xor_sync(~0u, acc[i], off);
                if (tq == 0) {
                    float* po = out + (size_t)b * HS + rank * HR + r0;
                    #pragma unroll
                    for (int k = 0; k < 4; ++k) {
                        float4 o = {acc[4*k], acc[4*k+1], acc[4*k+2], acc[4*k+3]};
                        *reinterpret_cast<float4*>(po + 4 * k) = o;
                    }
                }
                #pragma unroll
                for (int i = 0; i < 16; ++i) acc[i] = 0.0f;
            }
        }
    }

    // no CTA may exit while peers can still write into its smem
    asm volatile("barrier.cluster.arrive.aligned;" ::: "memory");
    asm volatile("barrier.cluster.wait.aligned;" ::: "memory");
}

extern "C" void kernel_launch(void* const* d_in, const int* in_sizes, int n_in,
                              void* d_out, int out_size) {
    const float* dh  = (const float*)d_in[0];
    const float* enc = (const float*)d_in[1];
    if (n_in >= 2 && in_sizes[0] > in_sizes[1]) {
        enc = (const float*)d_in[0];
        dh  = (const float*)d_in[1];
    }
    float* out = (float*)d_out;

    cudaFuncSetAttribute(attn_main,
                         cudaFuncAttributeMaxDynamicSharedMemorySize, SMEM_BYTES);
    attn_main<<<GRID, THREADS, SMEM_BYTES>>>(dh, enc, out);
}

// round 7
// speedup vs baseline: 1.5276x; 1.5276x over previous
#include <cuda_runtime.h>
#include <cuda.h>
#include <math.h>
#include <stdint.h>

// Fixed shape: H=1024, B=64, T=1024
#define BB 64
#define TS 1024
#define HS 1024
#define TCH 16                       // t per tile
#define NTILES 4096                  // 64 b * 64 t-chunks
#define GRIDN 152                    // GB300: 152 SMs, one persistent CTA each
#define NTHR 256
#define DEPTH 3
#define TILE_FLOATS (HS * TCH)       // 16384
#define TILE_BYTES (TILE_FLOATS * 4) // 64 KB

// dynamic smem layout (floats)
#define F_DH   (DEPTH * TILE_FLOATS)     // dh slice: 1024 floats
#define F_SRED (F_DH + HS)               // sred: [4 kinds][8 w][16 t] = 512 floats
#define F_END  (F_SRED + 512)
#define B_MBAR (F_END * 4)               // byte offset of mbarriers
#define SMEM_BYTES (B_MBAR + DEPTH * 8)  // ~202.8 KB

__device__ __forceinline__ uint32_t smem_u32(const void* p) {
    return (uint32_t)__cvta_generic_to_shared(p);
}
__device__ __forceinline__ void mbar_init(uint32_t a, uint32_t cnt) {
    asm volatile("mbarrier.init.shared.b64 [%0], %1;" :: "r"(a), "r"(cnt) : "memory");
}
#define MB_WAIT(addr, parity) do {                                              \
    uint32_t _m = (addr), _p = (parity), _d;                                    \
    asm volatile("{\n\t.reg .pred p;\n\t"                                       \
        "mbarrier.try_wait.parity.acquire.cta.shared::cta.b64 p, [%1], %2;\n\t" \
        "selp.b32 %0, 1, 0, p;\n\t}" : "=r"(_d) : "r"(_m), "r"(_p) : "memory"); \
    if (!_d) {                                                                  \
        asm volatile("{\n\t.reg .pred P1;\n\tW%=:\n\t"                          \
            "mbarrier.try_wait.parity.acquire.cta.shared::cta.b64 P1, [%0], %1, 0x989680;\n\t" \
            "@P1 bra.uni D%=;\n\tbra.uni W%=;\n\tD%=:\n\t}"                     \
            :: "r"(_m), "r"(_p) : "memory");                                    \
    }                                                                           \
} while (0)

// Issue one 64KB tile (tile id m) into ring slot s: expect_tx + 4 x 3D TMA.
__device__ __forceinline__ void tma_issue(const CUtensorMap& tmap, uint32_t sb,
                                          uint32_t MB, int s, int m) {
    const int c = m & 63, b = m >> 6;
    const uint32_t mb = MB + (uint32_t)s * 8;
    asm volatile("mbarrier.arrive.expect_tx.shared.b64 _, [%0], %1;"
                 :: "r"(mb), "r"((uint32_t)TILE_BYTES) : "memory");
    const uint32_t dst = sb + (uint32_t)s * TILE_BYTES;
    #pragma unroll
    for (int k = 0; k < 4; ++k) {
        asm volatile(
            "cp.async.bulk.tensor.3d.shared::cta.global.tile.mbarrier::complete_tx::bytes "
            "[%0], [%1, {%2, %3, %4}], [%5];"
            :: "r"(dst + (uint32_t)k * 16384), "l"(&tmap),
               "r"(c * TCH), "r"(b), "r"(k * 256), "r"(mb) : "memory");
    }
}

// In-register 16x16 transpose-reduce over half-warp lanes (hw = lane & 15).
// After: a[0] on lane hw == sum over the 16 lanes of column hw.
__device__ __forceinline__ void tr_reduce16(float* a, int hw) {
    #pragma unroll
    for (int s = 8; s >= 1; s >>= 1) {
        const bool up = (hw & s) != 0;
        #pragma unroll
        for (int i = 0; i < s; ++i) {
            const float give = up ? a[i] : a[i + s];
            const float keep = up ? a[i + s] : a[i];
            const float got  = __shfl_xor_sync(0xffffffffu, give, s);
            a[i] = keep + got;
        }
    }
}

__global__ void __launch_bounds__(1024)
zero_out(float* __restrict__ out) {
    out[blockIdx.x * 1024 + threadIdx.x] = 0.0f;
}

__global__ void __launch_bounds__(NTHR, 1)
attn_main(const __grid_constant__ CUtensorMap tmap,
          const float* __restrict__ dh, float* __restrict__ out) {
    extern __shared__ float smem[];
    const uint32_t sb = smem_u32(smem);
    const uint32_t MB = sb + B_MBAR;
    float* dhs  = smem + F_DH;
    float* sred = smem + F_SRED;

    const int tid = threadIdx.x;
    const int w = tid >> 5, l = tid & 31;
    const int t = l & 15, hr = l >> 4;
    const int rb = w * 128 + hr;      // rows rb, rb+2, ..., rb+126 (64 rows, fixed t)

    const int bid = blockIdx.x;
    const int nt = (NTILES - bid + GRIDN - 1) / GRIDN;

    if (tid == 0)
        for (int s = 0; s < DEPTH; ++s) mbar_init(MB + s * 8, 1);
    __syncthreads();

    if (tid == 0)
        for (int k = 0; k < DEPTH && k < nt; ++k)
            tma_issue(tmap, sb, MB, k, bid + k * GRIDN);

    for (int n = 0; n < nt; ++n) {
        const int m = bid + n * GRIDN;
        const int b = m >> 6;
        const int s = n % DEPTH;

        // dh slice for this b (L2-resident after first sweep)
        const float4 dv = __ldg(reinterpret_cast<const float4*>(dh + b * HS) + tid);
        MB_WAIT(MB + s * 8, (n / DEPTH) & 1);
        reinterpret_cast<float4*>(dhs)[tid] = dv;
        __syncthreads();                                 // #1: dh visible

        // ---- stat pass: tile -> registers, fused dot/max/min (conflict-free LDS) ----
        const float* tp = smem + s * TILE_FLOATS + rb * 16 + t;
        const float* dp = dhs + rb;
        float v[64];
        float sp = 0.f, mx = -INFINITY, mn = INFINITY;
        #pragma unroll
        for (int i = 0; i < 64; ++i) {
            v[i] = tp[i * 32];
            sp = fmaf(v[i], dp[i * 2], sp);              // dh read is 16-lane broadcast
            mx = fmaxf(mx, v[i]);
            mn = fminf(mn, v[i]);
        }
        sp += __shfl_xor_sync(~0u, sp, 16);
        mx = fmaxf(mx, __shfl_xor_sync(~0u, mx, 16));
        mn = fminf(mn, __shfl_xor_sync(~0u, mn, 16));
        if (l < 16) {
            sred[        w * 16 + l] = sp;
            sred[128 +   w * 16 + l] = mx;
            sred[256 +   w * 16 + l] = mn;
        }
        __syncthreads();   // #2: stats posted AND everyone done reading slot s

        // refill slot s with tile n+DEPTH (slot proven free by #2)
        if (tid == 0 && n + DEPTH < nt)
            tma_issue(tmap, sb, MB, s, bid + (n + DEPTH) * GRIDN);

        // full-H stats for my t
        float sc = 0.f, X = -INFINITY, N = INFINITY;
        #pragma unroll
        for (int w2 = 0; w2 < 8; ++w2) {
            sc += sred[w2 * 16 + t];
            X = fmaxf(X, sred[128 + w2 * 16 + t]);
            N = fminf(N, sred[256 + w2 * 16 + t]);
        }
        const float M = (sc >= 0.f) ? X * sc : N * sc;   // exact max_h(v*s)

        // ---- exp on registers + denominator ----
        float ds = 0.f;
        #pragma unroll
        for (int i = 0; i < 64; ++i) {
            v[i] = __expf(fmaf(v[i], sc, -M));
            ds += v[i];
        }
        ds += __shfl_xor_sync(~0u, ds, 16);
        if (l < 16) sred[384 + w * 16 + l] = ds;
        __syncthreads();   // #3

        float d = 0.f;
        #pragma unroll
        for (int w2 = 0; w2 < 8; ++w2) d += sred[384 + w2 * 16 + t];
        const float inv = 1.0f / d;
        #pragma unroll
        for (int i = 0; i < 64; ++i) v[i] *= inv;

        // ---- per-row sums over the 16 t's, then atomic accumulate ----
        #pragma unroll
        for (int g = 0; g < 4; ++g) tr_reduce16(v + 16 * g, t);

        float* ob = out + b * HS + w * 128 + 2 * t + hr;
        #pragma unroll
        for (int g = 0; g < 4; ++g)
            atomicAdd(ob + 32 * g, v[16 * g]);
    }
}

extern "C" void kernel_launch(void* const* d_in, const int* in_sizes, int n_in,
                              void* d_out, int out_size) {
    const float* dh  = (const float*)d_in[0];
    const float* enc = (const float*)d_in[1];
    if (n_in >= 2 && in_sizes[0] > in_sizes[1]) {
        enc = (const float*)d_in[0];
        dh  = (const float*)d_in[1];
    }
    float* out = (float*)d_out;

    // Build the TMA descriptor via the driver entry point (no -lcuda needed).
    typedef CUresult (*EncodeFn)(
        CUtensorMap*, CUtensorMapDataType, cuuint32_t, void*,
        const cuuint64_t*, const cuuint64_t*, const cuuint32_t*, const cuuint32_t*,
        CUtensorMapInterleave, CUtensorMapSwizzle, CUtensorMapL2promotion,
        CUtensorMapFloatOOBfill);
    void* fp = nullptr;
    cudaDriverEntryPointQueryResult qres;
#if CUDART_VERSION >= 12050
    cudaGetDriverEntryPointByVersion("cuTensorMapEncodeTiled", &fp, 12030,
                                     cudaEnableDefault, &qres);
#else
    cudaGetDriverEntryPoint("cuTensorMapEncodeTiled", &fp, cudaEnableDefault, &qres);
#endif
    CUtensorMap tmap;
    {
        EncodeFn fn = (EncodeFn)fp;
        cuuint64_t dims[3]    = {TS, BB, HS};                       // t, b, h
        cuuint64_t strides[2] = {TS * 4ull, (cuuint64_t)BB * TS * 4ull};
        cuuint32_t box[3]     = {TCH, 1, 256};
        cuuint32_t es[3]      = {1, 1, 1};
        fn(&tmap, CU_TENSOR_MAP_DATA_TYPE_FLOAT32, 3, (void*)enc,
           dims, strides, box, es,
           CU_TENSOR_MAP_INTERLEAVE_NONE, CU_TENSOR_MAP_SWIZZLE_NONE,
           CU_TENSOR_MAP_L2_PROMOTION_L2_128B, CU_TENSOR_MAP_FLOAT_OOB_FILL_NONE);
    }

    cudaFuncSetAttribute(attn_main,
                         cudaFuncAttributeMaxDynamicSharedMemorySize, SMEM_BYTES);
    zero_out<<<64, 1024>>>(out);
    attn_main<<<GRIDN, NTHR, SMEM_BYTES>>>(tmap, dh, out);
}

// round 8
// speedup vs baseline: 1.8613x; 1.2185x over previous
#include <cuda_runtime.h>
#include <cuda.h>
#include <math.h>
#include <stdint.h>

// Fixed shape: H=1024, B=64, T=1024
#define BB 64
#define TS 1024
#define HS 1024
#define TCH 16                       // t per tile
#define NTILES 4096                  // 64 b * 64 t-chunks
#define GRIDN 152
#define NTHR 512
#define DEPTH 3
#define TILE_FLOATS (HS * TCH)       // 16384
#define TILE_BYTES (TILE_FLOATS * 4) // 64 KB
#define L2E 1.44269504088896340736f

// dynamic smem layout (floats)
#define F_DH   (DEPTH * TILE_FLOATS)      // dh slice: 1024 floats
#define F_SRED (F_DH + HS)                // [4 kinds][16 w][16 t] = 1024 floats
#define F_FIN  (F_SRED + 1024)            // sc2[16] | M2[16] | inv[16]
#define F_END  (F_FIN + 48)
#define B_MBAR (F_END * 4)
#define SMEM_BYTES (B_MBAR + DEPTH * 8)   // ~205 KB

__device__ __forceinline__ uint32_t smem_u32(const void* p) {
    return (uint32_t)__cvta_generic_to_shared(p);
}
__device__ __forceinline__ void mbar_init(uint32_t a, uint32_t cnt) {
    asm volatile("mbarrier.init.shared.b64 [%0], %1;" :: "r"(a), "r"(cnt) : "memory");
}
#define MB_WAIT(addr, parity) do {                                              \
    uint32_t _m = (addr), _p = (parity), _d;                                    \
    asm volatile("{\n\t.reg .pred p;\n\t"                                       \
        "mbarrier.try_wait.parity.acquire.cta.shared::cta.b64 p, [%1], %2;\n\t" \
        "selp.b32 %0, 1, 0, p;\n\t}" : "=r"(_d) : "r"(_m), "r"(_p) : "memory"); \
    if (!_d) {                                                                  \
        asm volatile("{\n\t.reg .pred P1;\n\tW%=:\n\t"                          \
            "mbarrier.try_wait.parity.acquire.cta.shared::cta.b64 P1, [%0], %1, 0x989680;\n\t" \
            "@P1 bra.uni D%=;\n\tbra.uni W%=;\n\tD%=:\n\t}"                     \
            :: "r"(_m), "r"(_p) : "memory");                                    \
    }                                                                           \
} while (0)

// One 64KB tile (tile id m) into ring slot s: expect_tx + 4 x 3D TMA.
__device__ __forceinline__ void tma_issue(const CUtensorMap& tmap, uint32_t sb,
                                          uint32_t MB, int s, int m) {
    const int c = m & 63, b = m >> 6;
    const uint32_t mb = MB + (uint32_t)s * 8;
    asm volatile("mbarrier.arrive.expect_tx.shared.b64 _, [%0], %1;"
                 :: "r"(mb), "r"((uint32_t)TILE_BYTES) : "memory");
    const uint32_t dst = sb + (uint32_t)s * TILE_BYTES;
    #pragma unroll
    for (int k = 0; k < 4; ++k) {
        asm volatile(
            "cp.async.bulk.tensor.3d.shared::cta.global.tile.mbarrier::complete_tx::bytes "
            "[%0], [%1, {%2, %3, %4}], [%5];"
            :: "r"(dst + (uint32_t)k * 16384), "l"(&tmap),
               "r"(c * TCH), "r"(b), "r"(k * 256), "r"(mb) : "memory");
    }
}

// In-register 16x16 transpose-reduce over half-warp lanes (hw = lane & 15).
__device__ __forceinline__ void tr_reduce16(float* a, int hw) {
    #pragma unroll
    for (int s = 8; s >= 1; s >>= 1) {
        const bool up = (hw & s) != 0;
        #pragma unroll
        for (int i = 0; i < s; ++i) {
            const float give = up ? a[i] : a[i + s];
            const float keep = up ? a[i + s] : a[i];
            const float got  = __shfl_xor_sync(0xffffffffu, give, s);
            a[i] = keep + got;
        }
    }
}

__global__ void __launch_bounds__(1024)
zero_out(float* __restrict__ out) {
    out[blockIdx.x * 1024 + threadIdx.x] = 0.0f;
}

__global__ void __launch_bounds__(NTHR, 1)
attn_main(const __grid_constant__ CUtensorMap tmap,
          const float* __restrict__ dh, float* __restrict__ out) {
    extern __shared__ float smem[];
    const uint32_t sb = smem_u32(smem);
    const uint32_t MB = sb + B_MBAR;
    float* dhs  = smem + F_DH;
    float* sred = smem + F_SRED;
    float* fin  = smem + F_FIN;

    const int tid = threadIdx.x;
    const int w = tid >> 5, l = tid & 31;
    const int t = l & 15, hr = l >> 4;
    const int rb = w * 64 + hr;          // rows rb + 2*i, i < 32

    // consecutive tile range for this CTA
    const int start = (int)(((long long)blockIdx.x * NTILES) / GRIDN);
    const int end   = (int)(((long long)(blockIdx.x + 1) * NTILES) / GRIDN);
    const int nt    = end - start;

    if (tid == 0)
        for (int s = 0; s < DEPTH; ++s) mbar_init(MB + s * 8, 1);
    __syncthreads();

    if (tid == 0)
        for (int k = 0; k < DEPTH && k < nt; ++k)
            tma_issue(tmap, sb, MB, k, start + k);

    int bcur = -1;
    for (int n = 0; n < nt; ++n) {
        const int m = start + n;
        const int b = m >> 6;
        const int s = n % DEPTH;

        if (b != bcur) {                 // rare: ~1-2 times per CTA
            if (tid < 256) {
                reinterpret_cast<float4*>(dhs)[tid] =
                    __ldg(reinterpret_cast<const float4*>(dh + b * HS) + tid);
            }
            bcur = b;
            __syncthreads();             // dh visible before use
        }
        MB_WAIT(MB + s * 8, (n / DEPTH) & 1);

        // ---- stat pass: tile slice -> registers, fused dot/max/min ----
        const float* tp = smem + s * TILE_FLOATS + rb * 16 + t;
        const float* dp = dhs + rb;
        float v[32];
        float sp = 0.f, mx = -INFINITY, mn = INFINITY;
        #pragma unroll
        for (int i = 0; i < 32; ++i) {
            v[i] = tp[i * 32];           // bank = (hr*16 + t): conflict-free
            sp = fmaf(v[i], dp[i * 2], sp);
            mx = fmaxf(mx, v[i]);
            mn = fminf(mn, v[i]);
        }
        sp += __shfl_xor_sync(~0u, sp, 16);
        mx = fmaxf(mx, __shfl_xor_sync(~0u, mx, 16));
        mn = fminf(mn, __shfl_xor_sync(~0u, mn, 16));
        if (l < 16) {
            sred[        w * 16 + l] = sp;
            sred[256 +   w * 16 + l] = mx;
            sred[512 +   w * 16 + l] = mn;
        }
        __syncthreads();   // #1: stats posted AND slot s fully consumed

        // refill slot s (now provably free)
        if (tid == 0 && n + DEPTH < nt)
            tma_issue(tmap, sb, MB, s, m + DEPTH);

        // warp 0 publishes final per-t stats (sc, M) pre-scaled by log2e
        if (w == 0 && l < 16) {
            float sc = 0.f, X = -INFINITY, N = INFINITY;
            #pragma unroll
            for (int w2 = 0; w2 < 16; ++w2) {
                sc += sred[w2 * 16 + l];
                X = fmaxf(X, sred[256 + w2 * 16 + l]);
                N = fminf(N, sred[512 + w2 * 16 + l]);
            }
            const float M = (sc >= 0.f) ? X * sc : N * sc;   // exact max_h(v*s)
            fin[l]      = sc * L2E;
            fin[16 + l] = M * L2E;
        }
        __syncthreads();   // #2

        // ---- exp2 on registers + denominator ----
        const float scF = fin[t];
        const float MF  = fin[16 + t];
        float ds = 0.f;
        #pragma unroll
        for (int i = 0; i < 32; ++i) {
            v[i] = exp2f(fmaf(v[i], scF, -MF));
            ds += v[i];
        }
        ds += __shfl_xor_sync(~0u, ds, 16);
        if (l < 16) sred[768 + w * 16 + l] = ds;
        __syncthreads();   // #3

        if (w == 0 && l < 16) {
            float d = 0.f;
            #pragma unroll
            for (int w2 = 0; w2 < 16; ++w2) d += sred[768 + w2 * 16 + l];
            fin[32 + l] = 1.0f / d;
        }
        __syncthreads();   // #4

        const float inv = fin[32 + t];
        #pragma unroll
        for (int i = 0; i < 32; ++i) v[i] *= inv;

        // ---- per-row sums over the 16 t's, then atomic accumulate ----
        tr_reduce16(v, t);
        tr_reduce16(v + 16, t);
        // lane (hr,t), group g -> row w*64 + hr + 32*g + 2*t
        float* ob = out + b * HS + w * 64 + hr + 2 * t;
        atomicAdd(ob,      v[0]);
        atomicAdd(ob + 32, v[16]);
    }
}

extern "C" void kernel_launch(void* const* d_in, const int* in_sizes, int n_in,
                              void* d_out, int out_size) {
    const float* dh  = (const float*)d_in[0];
    const float* enc = (const float*)d_in[1];
    if (n_in >= 2 && in_sizes[0] > in_sizes[1]) {
        enc = (const float*)d_in[0];
        dh  = (const float*)d_in[1];
    }
    float* out = (float*)d_out;

    typedef CUresult (*EncodeFn)(
        CUtensorMap*, CUtensorMapDataType, cuuint32_t, void*,
        const cuuint64_t*, const cuuint64_t*, const cuuint32_t*, const cuuint32_t*,
        CUtensorMapInterleave, CUtensorMapSwizzle, CUtensorMapL2promotion,
        CUtensorMapFloatOOBfill);
    void* fp = nullptr;
    cudaDriverEntryPointQueryResult qres;
#if CUDART_VERSION >= 12050
    cudaGetDriverEntryPointByVersion("cuTensorMapEncodeTiled", &fp, 12030,
                                     cudaEnableDefault, &qres);
#else
    cudaGetDriverEntryPoint("cuTensorMapEncodeTiled", &fp, cudaEnableDefault, &qres);
#endif
    CUtensorMap tmap;
    {
        EncodeFn fn = (EncodeFn)fp;
        cuuint64_t dims[3]    = {TS, BB, HS};
        cuuint64_t strides[2] = {TS * 4ull, (cuuint64_t)BB * TS * 4ull};
        cuuint32_t box[3]     = {TCH, 1, 256};
        cuuint32_t es[3]      = {1, 1, 1};
        fn(&tmap, CU_TENSOR_MAP_DATA_TYPE_FLOAT32, 3, (void*)enc,
           dims, strides, box, es,
           CU_TENSOR_MAP_INTERLEAVE_NONE, CU_TENSOR_MAP_SWIZZLE_NONE,
           CU_TENSOR_MAP_L2_PROMOTION_L2_128B, CU_TENSOR_MAP_FLOAT_OOB_FILL_NONE);
    }

    cudaFuncSetAttribute(attn_main,
                         cudaFuncAttributeMaxDynamicSharedMemorySize, SMEM_BYTES);
    zero_out<<<64, 1024>>>(out);
    attn_main<<<GRIDN, NTHR, SMEM_BYTES>>>(tmap, dh, out);
}

// round 9
// speedup vs baseline: 1.9766x; 1.0619x over previous
#include <cuda_runtime.h>
#include <cuda.h>
#include <math.h>
#include <stdint.h>

// Fixed shape: H=1024, B=64, T=1024
#define BB 64
#define TS 1024
#define HS 1024
#define TCH 16                       // t per tile
#define NTILES 4096                  // 64 b * 64 t-chunks
#define GRIDN 152
#define NTHR 512
#define DEPTH 3
#define TILE_FLOATS (HS * TCH)       // 16384
#define TILE_BYTES (TILE_FLOATS * 4) // 64 KB
#define L2E 1.44269504088896340736f

// dynamic smem layout (floats)
#define F_DH   (DEPTH * TILE_FLOATS)      // dh slice: 1024 floats
#define F_SRED (F_DH + HS)                // [4 kinds][16 w][16 t] = 1024 floats
#define F_FIN  (F_SRED + 1024)            // sc2[16] | M2[16] | inv[16]
#define F_END  (F_FIN + 48)
#define B_MBAR (F_END * 4)
#define SMEM_BYTES (B_MBAR + DEPTH * 8)   // ~205 KB

__device__ __forceinline__ uint32_t smem_u32(const void* p) {
    return (uint32_t)__cvta_generic_to_shared(p);
}
__device__ __forceinline__ void mbar_init(uint32_t a, uint32_t cnt) {
    asm volatile("mbarrier.init.shared.b64 [%0], %1;" :: "r"(a), "r"(cnt) : "memory");
}
#define MB_WAIT(addr, parity) do {                                              \
    uint32_t _m = (addr), _p = (parity), _d;                                    \
    asm volatile("{\n\t.reg .pred p;\n\t"                                       \
        "mbarrier.try_wait.parity.acquire.cta.shared::cta.b64 p, [%1], %2;\n\t" \
        "selp.b32 %0, 1, 0, p;\n\t}" : "=r"(_d) : "r"(_m), "r"(_p) : "memory"); \
    if (!_d) {                                                                  \
        asm volatile("{\n\t.reg .pred P1;\n\tW%=:\n\t"                          \
            "mbarrier.try_wait.parity.acquire.cta.shared::cta.b64 P1, [%0], %1, 0x989680;\n\t" \
            "@P1 bra.uni D%=;\n\tbra.uni W%=;\n\tD%=:\n\t}"                     \
            :: "r"(_m), "r"(_p) : "memory");                                    \
    }                                                                           \
} while (0)

// One 64KB tile (tile id m) into ring slot s: expect_tx + 4 x 3D TMA.
__device__ __forceinline__ void tma_issue(const CUtensorMap& tmap, uint32_t sb,
                                          uint32_t MB, int s, int m) {
    const int c = m & 63, b = m >> 6;
    const uint32_t mb = MB + (uint32_t)s * 8;
    asm volatile("mbarrier.arrive.expect_tx.shared.b64 _, [%0], %1;"
                 :: "r"(mb), "r"((uint32_t)TILE_BYTES) : "memory");
    const uint32_t dst = sb + (uint32_t)s * TILE_BYTES;
    #pragma unroll
    for (int k = 0; k < 4; ++k) {
        asm volatile(
            "cp.async.bulk.tensor.3d.shared::cta.global.tile.mbarrier::complete_tx::bytes "
            "[%0], [%1, {%2, %3, %4}], [%5];"
            :: "r"(dst + (uint32_t)k * 16384), "l"(&tmap),
               "r"(c * TCH), "r"(b), "r"(k * 256), "r"(mb) : "memory");
    }
}

// In-register 16x16 transpose-reduce over half-warp lanes (hw = lane & 15).
__device__ __forceinline__ void tr_reduce16(float* a, int hw) {
    #pragma unroll
    for (int s = 8; s >= 1; s >>= 1) {
        const bool up = (hw & s) != 0;
        #pragma unroll
        for (int i = 0; i < s; ++i) {
            const float give = up ? a[i] : a[i + s];
            const float keep = up ? a[i + s] : a[i];
            const float got  = __shfl_xor_sync(0xffffffffu, give, s);
            a[i] = keep + got;
        }
    }
}

__global__ void __launch_bounds__(1024)
zero_out(float* __restrict__ out) {
    out[blockIdx.x * 1024 + threadIdx.x] = 0.0f;
}

__global__ void __launch_bounds__(NTHR, 1)
attn_main(const __grid_constant__ CUtensorMap tmap,
          const float* __restrict__ dh, float* __restrict__ out) {
    extern __shared__ float smem[];
    const uint32_t sb = smem_u32(smem);
    const uint32_t MB = sb + B_MBAR;
    float* dhs  = smem + F_DH;
    float* sred = smem + F_SRED;
    float* fin  = smem + F_FIN;

    const int tid = threadIdx.x;
    const int w = tid >> 5, l = tid & 31;
    const int t = l & 15, hr = l >> 4;
    const int rb = w * 64 + hr;          // rows rb + 2*i, i < 32

    // consecutive tile range for this CTA (same-b runs -> register accumulation)
    const int start = (int)(((long long)blockIdx.x * NTILES) / GRIDN);
    const int end   = (int)(((long long)(blockIdx.x + 1) * NTILES) / GRIDN);
    const int nt    = end - start;

    if (tid == 0)
        for (int s = 0; s < DEPTH; ++s) mbar_init(MB + s * 8, 1);
    __syncthreads();

    if (tid == 0)
        for (int k = 0; k < DEPTH && k < nt; ++k)
            tma_issue(tmap, sb, MB, k, start + k);

    float acc[32];
    #pragma unroll
    for (int i = 0; i < 32; ++i) acc[i] = 0.0f;

    int bcur = -1;
    for (int n = 0; n < nt; ++n) {
        const int m = start + n;
        const int b = m >> 6;
        const int s = n % DEPTH;

        if (b != bcur) {                 // rare: ~1-2 times per CTA
            if (bcur >= 0) {
                // flush accumulated per-row sums for previous b
                tr_reduce16(acc, t);
                tr_reduce16(acc + 16, t);
                float* ob = out + bcur * HS + w * 64 + hr + 2 * t;
                atomicAdd(ob,      acc[0]);
                atomicAdd(ob + 32, acc[16]);
                #pragma unroll
                for (int i = 0; i < 32; ++i) acc[i] = 0.0f;
            }
            if (tid < 256) {
                reinterpret_cast<float4*>(dhs)[tid] =
                    __ldg(reinterpret_cast<const float4*>(dh + b * HS) + tid);
            }
            bcur = b;
            __syncthreads();             // dh visible before use
        }
        MB_WAIT(MB + s * 8, (n / DEPTH) & 1);

        // ---- stat pass: tile slice -> registers, fused dot/max/min ----
        const float* tp = smem + s * TILE_FLOATS + rb * 16 + t;
        const float* dp = dhs + rb;
        float v[32];
        float sp = 0.f, mx = -INFINITY, mn = INFINITY;
        #pragma unroll
        for (int i = 0; i < 32; ++i) {
            v[i] = tp[i * 32];           // bank = (hr*16 + t): conflict-free
            sp = fmaf(v[i], dp[i * 2], sp);
            mx = fmaxf(mx, v[i]);
            mn = fminf(mn, v[i]);
        }
        sp += __shfl_xor_sync(~0u, sp, 16);
        mx = fmaxf(mx, __shfl_xor_sync(~0u, mx, 16));
        mn = fminf(mn, __shfl_xor_sync(~0u, mn, 16));
        if (l < 16) {
            sred[        w * 16 + l] = sp;
            sred[256 +   w * 16 + l] = mx;
            sred[512 +   w * 16 + l] = mn;
        }
        __syncthreads();   // #1: stats posted AND slot s fully consumed

        // refill slot s (now provably free)
        if (tid == 0 && n + DEPTH < nt)
            tma_issue(tmap, sb, MB, s, m + DEPTH);

        // warp 0 publishes final per-t stats (sc, M) pre-scaled by log2e
        if (w == 0 && l < 16) {
            float sc = 0.f, X = -INFINITY, N = INFINITY;
            #pragma unroll
            for (int w2 = 0; w2 < 16; ++w2) {
                sc += sred[w2 * 16 + l];
                X = fmaxf(X, sred[256 + w2 * 16 + l]);
                N = fminf(N, sred[512 + w2 * 16 + l]);
            }
            const float M = (sc >= 0.f) ? X * sc : N * sc;   // exact max_h(v*s)
            fin[l]      = sc * L2E;
            fin[16 + l] = M * L2E;
        }
        __syncthreads();   // #2

        // ---- exp2 on registers + denominator ----
        const float scF = fin[t];
        const float MF  = fin[16 + t];
        float ds = 0.f;
        #pragma unroll
        for (int i = 0; i < 32; ++i) {
            v[i] = exp2f(fmaf(v[i], scF, -MF));
            ds += v[i];
        }
        ds += __shfl_xor_sync(~0u, ds, 16);
        if (l < 16) sred[768 + w * 16 + l] = ds;
        __syncthreads();   // #3

        if (w == 0 && l < 16) {
            float d = 0.f;
            #pragma unroll
            for (int w2 = 0; w2 < 16; ++w2) d += sred[768 + w2 * 16 + l];
            fin[32 + l] = 1.0f / d;
        }
        __syncthreads();   // #4

        // fold this tile into the per-row register accumulators
        const float inv = fin[32 + t];
        #pragma unroll
        for (int i = 0; i < 32; ++i)
            acc[i] = fmaf(v[i], inv, acc[i]);
    }

    // final flush for the last b
    if (bcur >= 0) {
        tr_reduce16(acc, t);
        tr_reduce16(acc + 16, t);
        float* ob = out + bcur * HS + w * 64 + hr + 2 * t;
        atomicAdd(ob,      acc[0]);
        atomicAdd(ob + 32, acc[16]);
    }
}

extern "C" void kernel_launch(void* const* d_in, const int* in_sizes, int n_in,
                              void* d_out, int out_size) {
    const float* dh  = (const float*)d_in[0];
    const float* enc = (const float*)d_in[1];
    if (n_in >= 2 && in_sizes[0] > in_sizes[1]) {
        enc = (const float*)d_in[0];
        dh  = (const float*)d_in[1];
    }
    float* out = (float*)d_out;

    typedef CUresult (*EncodeFn)(
        CUtensorMap*, CUtensorMapDataType, cuuint32_t, void*,
        const cuuint64_t*, const cuuint64_t*, const cuuint32_t*, const cuuint32_t*,
        CUtensorMapInterleave, CUtensorMapSwizzle, CUtensorMapL2promotion,
        CUtensorMapFloatOOBfill);
    void* fp = nullptr;
    cudaDriverEntryPointQueryResult qres;
#if CUDART_VERSION >= 12050
    cudaGetDriverEntryPointByVersion("cuTensorMapEncodeTiled", &fp, 12030,
                                     cudaEnableDefault, &qres);
#else
    cudaGetDriverEntryPoint("cuTensorMapEncodeTiled", &fp, cudaEnableDefault, &qres);
#endif
    CUtensorMap tmap;
    {
        EncodeFn fn = (EncodeFn)fp;
        cuuint64_t dims[3]    = {TS, BB, HS};
        cuuint64_t strides[2] = {TS * 4ull, (cuuint64_t)BB * TS * 4ull};
        cuuint32_t box[3]     = {TCH, 1, 256};
        cuuint32_t es[3]      = {1, 1, 1};
        fn(&tmap, CU_TENSOR_MAP_DATA_TYPE_FLOAT32, 3, (void*)enc,
           dims, strides, box, es,
           CU_TENSOR_MAP_INTERLEAVE_NONE, CU_TENSOR_MAP_SWIZZLE_NONE,
           CU_TENSOR_MAP_L2_PROMOTION_L2_128B, CU_TENSOR_MAP_FLOAT_OOB_FILL_NONE);
    }

    cudaFuncSetAttribute(attn_main,
                         cudaFuncAttributeMaxDynamicSharedMemorySize, SMEM_BYTES);
    zero_out<<<64, 1024>>>(out);
    attn_main<<<GRIDN, NTHR, SMEM_BYTES>>>(tmap, dh, out);
}